// round 5
// baseline (speedup 1.0000x reference)
#include <cuda_runtime.h>
#include <cuda_bf16.h>
#include <math.h>

// ---------------- problem constants ----------------
#define U_NN   50000
#define I_NN   25000
#define DD     64
#define DT     192
#define RR     2
#define LL     2
#define E_UI   500000
#define E_TR   600000
#define E_II   400000
#define BB     512
#define KK     100
#define EPSV   1e-8f

// CSR: 4 graphs.
//  gU: merged rel (dst=user, src=item packed with r in bit16), 1M edges
//  g2: train (dst=item, src=user)   g3/g4: ig r=0/1 (dst=item, src=item)
#define NTOT   125000            // 50000 + 3*25000
#define ETOT   2400000
#define DBU 0
#define DB2 50000
#define DB3 75000
#define DB4 100000
#define EBU 0
#define EB2 1000000
#define EB3 1600000
#define EB4 2000000
#define RBIT 0x10000

// ---------------- device scratch ----------------
__device__ __align__(16) float g_Uf[U_NN * DT];
__device__ __align__(16) float g_If[I_NN * DT];
__device__ __align__(16) float g_Sf[RR][I_NN * DT];
__device__ __align__(16) float g_Uagg[U_NN * DD];
__device__ __align__(16) float g_Iagg[I_NN * DD];
__device__ __align__(16) float g_IGagg[RR][I_NN * DD];
__device__            float g_cuser[U_NN * RR];
__device__            float g_invig[RR][I_NN];
__device__            float g_invdeg[I_NN];
__device__            int   g_cnt[NTOT];      // INVARIANT: zero at kernel_launch entry
__device__            int   g_off[NTOT];
__device__            int   g_cur[NTOT];
__device__            int   g_srcA[ETOT];
__device__ __align__(16) float g_G[RR][DT * DT];
__device__ __align__(16) float g_z[RR][BB * DT];

// ---------------- launch 1: init (copies/coeffs) + histogram -------------
__global__ void k_init_hist(const float* __restrict__ ue, const float* __restrict__ ie,
                            const int* __restrict__ ubd, const int* __restrict__ igd,
                            const float* __restrict__ mgnn,
                            const int* __restrict__ rel_r, const int* __restrict__ tr_c,
                            const int* __restrict__ ig_r) {
    int t = blockIdx.x * blockDim.x + threadIdx.x;
    // histogram (g_cnt is zero on entry by invariant)
    if (t < ETOT) {
        int d;
        if (t < EB2)       d = DBU + rel_r[t];                 // both rel halves -> same user bins
        else if (t < EB3)  d = DB2 + tr_c[t - EB2];
        else if (t < EB4)  d = DB3 + ig_r[t - EB3];
        else               d = DB4 + ig_r[E_II + (t - EB4)];
        atomicAdd(&g_cnt[d], 1);
    }
    if (t < U_NN) {
        float m0 = mgnn[0], m1 = mgnn[1];
        float mx = fmaxf(m0, m1);
        float e0 = expf(m0 - mx), e1 = expf(m1 - mx);
        float inv = 1.0f / (e0 + e1);
        float w0 = e0 * inv, w1 = e1 * inv;
        float d0 = (float)ubd[t * 2 + 0], d1 = (float)ubd[t * 2 + 1];
        float itot = 1.0f / (d0 * w0 + d1 * w1 + EPSV);
        g_cuser[t * 2 + 0] = d0 * w0 * itot / (d0 + EPSV);
        g_cuser[t * 2 + 1] = d1 * w1 * itot / (d1 + EPSV);
    }
    if (t < I_NN) {
        g_invig[0][t] = 1.0f / ((float)igd[0 * I_NN + t] + EPSV);
        g_invig[1][t] = 1.0f / ((float)igd[1 * I_NN + t] + EPSV);
    }
    int nU = U_NN * DD;
    if (t < nU) {
        int u = t >> 6, c = t & 63;
        g_Uf[u * DT + c] = ue[t];
    } else if (t < nU + I_NN * DD) {
        int j = t - nU;
        int i = j >> 6, c = j & 63;
        float v = ie[j];
        g_If[i * DT + c] = v;
        g_Sf[0][i * DT + c] = v;
        g_Sf[1][i * DT + c] = v;
    }
}

// ---------------- launch 2: scan (offsets + cursors + invdeg) -------------
__global__ void k_scan() {
    __shared__ int sh[1024];
    const int DBv[4] = {DBU, DB2, DB3, DB4};
    const int DSv[4] = {U_NN, I_NN, I_NN, I_NN};
    int gsel = blockIdx.x;
    int base = DBv[gsel], size = DSv[gsel];
    int t = threadIdx.x;
    int chunk = (size + 1023) >> 10;
    int lo = t * chunk;
    int hi = lo + chunk; if (hi > size) hi = size;
    if (lo > size) lo = size;
    int s = 0;
    for (int i = lo; i < hi; i++) s += g_cnt[base + i];
    sh[t] = s;
    __syncthreads();
    for (int off = 1; off < 1024; off <<= 1) {
        int v = (t >= off) ? sh[t - off] : 0;
        __syncthreads();
        sh[t] += v;
        __syncthreads();
    }
    int run = (t > 0) ? sh[t - 1] : 0;
    for (int i = lo; i < hi; i++) {
        g_off[base + i] = run;
        g_cur[base + i] = run;
        run += g_cnt[base + i];
    }
    if (gsel == 1) {
        for (int i = lo; i < hi; i++)
            g_invdeg[i] = 1.0f / ((float)g_cnt[DB2 + i] + EPSV);
    }
}

// ---------------- launch 3: place ----------------
__global__ void k_place_all(const int* __restrict__ rel_r, const int* __restrict__ rel_c,
                            const int* __restrict__ tr_r, const int* __restrict__ tr_c,
                            const int* __restrict__ ig_r, const int* __restrict__ ig_c) {
    int e = blockIdx.x * blockDim.x + threadIdx.x;
    if (e >= ETOT) return;
    int d, src, ebase;
    if (e < EB2) {
        d = DBU + rel_r[e];
        src = rel_c[e] + ((e >= E_UI) ? RBIT : 0);
        ebase = EBU;
    } else if (e < EB3) {
        int j = e - EB2; d = DB2 + tr_c[j]; src = tr_r[j]; ebase = EB2;
    } else if (e < EB4) {
        int j = e - EB3; d = DB3 + ig_r[j]; src = ig_c[j]; ebase = EB3;
    } else {
        int j = e - EB4; d = DB4 + ig_r[E_II + j]; src = ig_c[E_II + j]; ebase = EB4;
    }
    int p = atomicAdd(&g_cur[d], 1);
    g_srcA[ebase + p] = src;
}

// ---------------- gather (half-warp per edge, 4 independent chains) -------
template <bool WEIGHTED>
__device__ __forceinline__ float4 warp_gather_sum(const int* __restrict__ lst, int deg,
                                                  const float* __restrict__ fb,
                                                  int lane, int half,
                                                  float c0, float c1) {
    float4 a0 = {0.f,0.f,0.f,0.f}, a1 = {0.f,0.f,0.f,0.f};
    float4 a2 = {0.f,0.f,0.f,0.f}, a3 = {0.f,0.f,0.f,0.f};
    for (int j0 = 0; j0 < deg; j0 += 32) {
        int rem = deg - j0;
        int m = rem < 32 ? rem : 32;
        int my = (j0 + lane < deg) ? __ldg(&lst[j0 + lane]) : 0;
        int k = 0;
        for (; k + 8 <= m; k += 8) {
            int p0 = __shfl_sync(0xffffffffu, my, k + half);
            int p1 = __shfl_sync(0xffffffffu, my, k + 2 + half);
            int p2 = __shfl_sync(0xffffffffu, my, k + 4 + half);
            int p3 = __shfl_sync(0xffffffffu, my, k + 6 + half);
            int i0 = p0, i1 = p1, i2 = p2, i3 = p3;
            float w0 = 1.f, w1 = 1.f, w2 = 1.f, w3 = 1.f;
            if (WEIGHTED) {
                i0 = p0 & 0xFFFF; w0 = (p0 & RBIT) ? c1 : c0;
                i1 = p1 & 0xFFFF; w1 = (p1 & RBIT) ? c1 : c0;
                i2 = p2 & 0xFFFF; w2 = (p2 & RBIT) ? c1 : c0;
                i3 = p3 & 0xFFFF; w3 = (p3 & RBIT) ? c1 : c0;
            }
            float4 v0 = *reinterpret_cast<const float4*>(fb + (long)i0 * DT);
            float4 v1 = *reinterpret_cast<const float4*>(fb + (long)i1 * DT);
            float4 v2 = *reinterpret_cast<const float4*>(fb + (long)i2 * DT);
            float4 v3 = *reinterpret_cast<const float4*>(fb + (long)i3 * DT);
            a0.x += w0 * v0.x; a0.y += w0 * v0.y; a0.z += w0 * v0.z; a0.w += w0 * v0.w;
            a1.x += w1 * v1.x; a1.y += w1 * v1.y; a1.z += w1 * v1.z; a1.w += w1 * v1.w;
            a2.x += w2 * v2.x; a2.y += w2 * v2.y; a2.z += w2 * v2.z; a2.w += w2 * v2.w;
            a3.x += w3 * v3.x; a3.y += w3 * v3.y; a3.z += w3 * v3.z; a3.w += w3 * v3.w;
        }
        for (; k < m; k += 2) {
            int kk = k + half;
            int p = __shfl_sync(0xffffffffu, my, kk & 31);
            if (kk < m) {
                int idx = p; float w = 1.f;
                if (WEIGHTED) { idx = p & 0xFFFF; w = (p & RBIT) ? c1 : c0; }
                float4 v = *reinterpret_cast<const float4*>(fb + (long)idx * DT);
                a0.x += w * v.x; a0.y += w * v.y; a0.z += w * v.z; a0.w += w * v.w;
            }
        }
    }
    a0.x += a1.x + a2.x + a3.x;
    a0.y += a1.y + a2.y + a3.y;
    a0.z += a1.z + a2.z + a3.z;
    a0.w += a1.w + a2.w + a3.w;
    return a0;
}

// ---------------- launch 4/6: fused gather ----------------
__global__ void k_gather_all(int colOff) {
    int w = (blockIdx.x * blockDim.x + threadIdx.x) >> 5;
    if (w >= U_NN + 3 * I_NN) return;
    int lane = threadIdx.x & 31, half = lane >> 4, li = lane & 15;
    float4 r;
    float* dst;
    int row;
    if (w < U_NN) {
        int u = w;
        const float* fb = g_If + colOff + li * 4;
        float c0 = g_cuser[u * 2 + 0], c1 = g_cuser[u * 2 + 1];
        r = warp_gather_sum<true>(g_srcA + g_off[DBU + u], g_cnt[DBU + u],
                                  fb, lane, half, c0, c1);
        dst = g_Uagg; row = u;
    } else {
        int v = w - U_NN;
        int gsel = v / I_NN;
        int i = v - gsel * I_NN;
        float4 a; float c;
        if (gsel == 0) {
            a = warp_gather_sum<false>(g_srcA + EB2 + g_off[DB2 + i], g_cnt[DB2 + i],
                                       g_Uf + colOff + li * 4, lane, half, 0.f, 0.f);
            c = g_invdeg[i]; dst = g_Iagg;
        } else if (gsel == 1) {
            a = warp_gather_sum<false>(g_srcA + EB3 + g_off[DB3 + i], g_cnt[DB3 + i],
                                       g_If + colOff + li * 4, lane, half, 0.f, 0.f);
            c = g_invig[0][i]; dst = g_IGagg[0];
        } else {
            a = warp_gather_sum<false>(g_srcA + EB4 + g_off[DB4 + i], g_cnt[DB4 + i],
                                       g_If + colOff + li * 4, lane, half, 0.f, 0.f);
            c = g_invig[1][i]; dst = g_IGagg[1];
        }
        r = make_float4(a.x * c, a.y * c, a.z * c, a.w * c);
        row = i;
    }
    r.x += __shfl_xor_sync(0xffffffffu, r.x, 16);
    r.y += __shfl_xor_sync(0xffffffffu, r.y, 16);
    r.z += __shfl_xor_sync(0xffffffffu, r.z, 16);
    r.w += __shfl_xor_sync(0xffffffffu, r.w, 16);
    if (half == 0)
        *reinterpret_cast<float4*>(&dst[(long)row * DD + li * 4]) = r;
}

// ---------------- launch 5/7: fused dense projections ----------------
__global__ void k_gemm_all(const float* __restrict__ W_ui_l,
                           const float* __restrict__ W_ii0_l,
                           const float* __restrict__ W_ii1_l, int colOut) {
    __shared__ __align__(16) float Ws[64 * 64];
    __shared__ __align__(16) float As[64 * 68];
    int sel = blockIdx.y;
    const float* src; float* dst; const float* W; int N;
    if (sel == 0)      { src = g_Uagg;     dst = g_Uf;    W = W_ui_l;  N = U_NN; }
    else if (sel == 1) { src = g_Iagg;     dst = g_If;    W = W_ui_l;  N = I_NN; }
    else if (sel == 2) { src = g_IGagg[0]; dst = g_Sf[0]; W = W_ii0_l; N = I_NN; }
    else               { src = g_IGagg[1]; dst = g_Sf[1]; W = W_ii1_l; N = I_NN; }
    int row0 = blockIdx.x * 64;
    if (row0 >= N) return;
    int tid = threadIdx.x;

    for (int i = tid; i < 4096; i += 256) Ws[i] = W[i];
    for (int i = tid; i < 4096; i += 256) {
        int rr = i >> 6, k = i & 63;
        float v = (row0 + rr < N) ? src[(long)(row0 + rr) * DD + k] : 0.f;
        As[k * 68 + rr] = v;
    }
    __syncthreads();

    int cg = tid & 15, rg = tid >> 4;
    float acc[4][4];
#pragma unroll
    for (int i = 0; i < 4; i++)
#pragma unroll
        for (int j = 0; j < 4; j++) acc[i][j] = 0.f;

#pragma unroll 8
    for (int k = 0; k < 64; k++) {
        float4 a4 = *reinterpret_cast<const float4*>(&As[k * 68 + rg * 4]);
        float4 w4 = *reinterpret_cast<const float4*>(&Ws[k * 64 + cg * 4]);
        float a[4] = {a4.x, a4.y, a4.z, a4.w};
        float w[4] = {w4.x, w4.y, w4.z, w4.w};
#pragma unroll
        for (int i = 0; i < 4; i++)
#pragma unroll
            for (int j = 0; j < 4; j++) acc[i][j] += a[i] * w[j];
    }
#pragma unroll
    for (int i = 0; i < 4; i++) {
        int row = row0 + rg * 4 + i;
        if (row < N) {
            float4 o = make_float4(acc[i][0], acc[i][1], acc[i][2], acc[i][3]);
            *reinterpret_cast<float4*>(&dst[(long)row * DT + colOut + cg * 4]) = o;
        }
    }
}

// ---------------- scoring ----------------
__global__ void k_G(const float* __restrict__ bW, float* out, int lossIdx) {
    __shared__ float Asm[32 * 192];
    __shared__ float Bsm[32 * 192];
    if (blockIdx.x == 0 && blockIdx.y == 0 && blockIdx.z == 0 && threadIdx.x == 0)
        out[lossIdx] = 0.f;
    int r = blockIdx.z;
    const float* W = bW + (long)r * DT * DT;
    int i0 = blockIdx.x * 32, j0 = blockIdx.y * 32;
    for (int t = threadIdx.x; t < 32 * 192; t += 256) {
        Asm[t] = W[(long)(i0 + t / 192) * DT + (t % 192)];
        Bsm[t] = W[(long)(j0 + t / 192) * DT + (t % 192)];
    }
    __syncthreads();
    int tj = threadIdx.x & 15, ti = threadIdx.x >> 4;
    float acc[2][2] = {{0.f, 0.f}, {0.f, 0.f}};
    for (int k = 0; k < 192; k++) {
        float a0 = Asm[(ti * 2 + 0) * 192 + k];
        float a1 = Asm[(ti * 2 + 1) * 192 + k];
        float b0 = Bsm[(tj * 2 + 0) * 192 + k];
        float b1 = Bsm[(tj * 2 + 1) * 192 + k];
        acc[0][0] += a0 * b0; acc[0][1] += a0 * b1;
        acc[1][0] += a1 * b0; acc[1][1] += a1 * b1;
    }
#pragma unroll
    for (int i = 0; i < 2; i++)
#pragma unroll
        for (int j = 0; j < 2; j++)
            g_G[r][(long)(i0 + ti * 2 + i) * DT + (j0 + tj * 2 + j)] = acc[i][j];
}

// block per (b,r): aggregate batched user's rel-r subset of merged list, then z = agg @ G
__global__ void k_aggsel_z(const int* __restrict__ users, const int* __restrict__ ubd) {
    __shared__ float as[DT];
    int b = blockIdx.x, r = blockIdx.y, c = threadIdx.x;
    int u = users[b];
    const int* lst = g_srcA + g_off[DBU + u];
    int deg = g_cnt[DBU + u];
    int want = r ? RBIT : 0;
    const float* S = g_Sf[r];
    float a0 = 0.f;
    for (int j = 0; j < deg; j++) {
        int p = __ldg(&lst[j]);
        if ((p & RBIT) == want)
            a0 += S[(long)(p & 0xFFFF) * DT + c];
    }
    float coeff = 1.0f / ((float)ubd[u * 2 + r] + EPSV);
    as[c] = a0 * coeff;
    __syncthreads();
    float acc = 0.f;
    const float* G = g_G[r];
#pragma unroll 4
    for (int k = 0; k < DT; k++) acc += as[k] * G[(long)k * DT + c];
    g_z[r][(long)b * DT + c] = acc;
}

// warp per (b,k); also restores the g_cnt==0 invariant for the next call
__global__ void k_score(const int* __restrict__ users, const int* __restrict__ items,
                        float* out, int lossIdx) {
    __shared__ float l2blk;
    // restore invariant: zero g_cnt (read last by k_aggsel_z, which ran before us)
    int tg = blockIdx.x * blockDim.x + threadIdx.x;
    if (tg < NTOT) g_cnt[tg] = 0;
    if (threadIdx.x == 0) l2blk = 0.f;
    __syncthreads();
    int w = tg >> 5;
    int lane = threadIdx.x & 31;
    if (w < BB * KK) {
        int b = w / KK;
        int kk = w - b * KK;
        int u = users[b];
        int it = items[w];
        float s1 = 0.f, s2a = 0.f, s2b = 0.f, l2i = 0.f, l2u = 0.f;
        for (int c = lane; c < DT; c += 32) {
            float bu = g_Uf[(long)u * DT + c];
            float bi = g_If[(long)it * DT + c];
            s1 += bu * bi;
            l2i += bi * bi;
            if (kk == 0) l2u += bu * bu;
            s2a += g_z[0][(long)b * DT + c] * g_Sf[0][(long)it * DT + c];
            s2b += g_z[1][(long)b * DT + c] * g_Sf[1][(long)it * DT + c];
        }
#pragma unroll
        for (int off = 16; off; off >>= 1) {
            s1  += __shfl_down_sync(0xffffffffu, s1, off);
            s2a += __shfl_down_sync(0xffffffffu, s2a, off);
            s2b += __shfl_down_sync(0xffffffffu, s2b, off);
            l2i += __shfl_down_sync(0xffffffffu, l2i, off);
            if (kk == 0) l2u += __shfl_down_sync(0xffffffffu, l2u, off);
        }
        if (lane == 0) {
            out[w] = 0.5f * s1 + 0.25f * (s2a + s2b);
            atomicAdd(&l2blk, l2i + (kk == 0 ? (float)KK * l2u : 0.f));
        }
    }
    __syncthreads();
    if (threadIdx.x == 0) atomicAdd(out + lossIdx, 1e-4f * l2blk);
}

// ---------------- launch ----------------
extern "C" void kernel_launch(void* const* d_in, const int* in_sizes, int n_in,
                              void* d_out, int out_size) {
    const float* ue    = (const float*)d_in[0];
    const float* ie    = (const float*)d_in[1];
    const float* W_ui  = (const float*)d_in[2];
    const float* W_ii  = (const float*)d_in[3];
    const float* bW    = (const float*)d_in[4];
    const float* mgnn  = (const float*)d_in[5];
    const int* rel_r   = (const int*)d_in[6];
    const int* rel_c   = (const int*)d_in[7];
    const int* tr_r    = (const int*)d_in[8];
    const int* tr_c    = (const int*)d_in[9];
    const int* ig_r    = (const int*)d_in[10];
    const int* ig_c    = (const int*)d_in[11];
    const int* ubd     = (const int*)d_in[12];
    const int* igd     = (const int*)d_in[13];
    const int* users   = (const int*)d_in[14];
    const int* items   = (const int*)d_in[15];
    float* out = (float*)d_out;
    int lossIdx = out_size - 1;

    const int T = 256;
    auto g = [](long n, int t) { return (int)((n + t - 1) / t); };

    // 1-3: init + CSR build (g_cnt zero-at-entry invariant; k_score restores it)
    k_init_hist<<<g((long)(U_NN + I_NN) * DD, T), T>>>(ue, ie, ubd, igd, mgnn,
                                                       rel_r, tr_c, ig_r);
    k_scan<<<4, 1024>>>();
    k_place_all<<<g(ETOT, T), T>>>(rel_r, rel_c, tr_r, tr_c, ig_r, ig_c);

    // 4-7: two propagation layers
    for (int l = 0; l < LL; l++) {
        k_gather_all<<<g((long)(U_NN + 3 * I_NN) * 32, T), T>>>(l * DD);
        dim3 gg(g(U_NN, 64), 4);
        k_gemm_all<<<gg, 256>>>(W_ui + (long)l * DD * DD,
                                W_ii + (long)(0 * LL + l) * DD * DD,
                                W_ii + (long)(1 * LL + l) * DD * DD,
                                (l + 1) * DD);
    }

    // 8-10: scoring
    {
        dim3 ggG(6, 6, 2);
        k_G<<<ggG, 256>>>(bW, out, lossIdx);
    }
    {
        dim3 gz(BB, RR);
        k_aggsel_z<<<gz, DT>>>(users, ubd);
    }
    k_score<<<g((long)BB * KK * 32, T), T>>>(users, items, out, lossIdx);
}

// round 6
// speedup vs baseline: 1.1291x; 1.1291x over previous
#include <cuda_runtime.h>
#include <cuda_bf16.h>
#include <math.h>

// ---------------- problem constants ----------------
#define U_NN   50000
#define I_NN   25000
#define DD     64
#define DT     192
#define RR     2
#define LL     2
#define E_UI   500000
#define E_TR   600000
#define E_II   400000
#define BB     512
#define KK     100
#define EPSV   1e-8f

// CSR: 4 graphs.
//  gU: merged rel (dst=user, src=item packed with r in bit16), 1M edges
//  g2: train (dst=item, src=user)   g3/g4: ig r=0/1 (dst=item, src=item)
#define NTOT   125000            // 50000 + 3*25000
#define ETOT   2400000
#define DBU 0
#define DB2 50000
#define DB3 75000
#define DB4 100000
#define EBU 0
#define EB2 1000000
#define EB3 1600000
#define EB4 2000000
#define RBIT 0x10000

// ---------------- device scratch ----------------
__device__ __align__(16) float g_Uf[U_NN * DT];
__device__ __align__(16) float g_If[I_NN * DT];
__device__ __align__(16) float g_Sf[RR][I_NN * DT];
__device__ __align__(16) float g_Uagg[U_NN * DD];
__device__ __align__(16) float g_Iagg[I_NN * DD];
__device__ __align__(16) float g_IGagg[RR][I_NN * DD];
__device__            float g_cuser[U_NN * RR];
__device__            float g_invig[RR][I_NN];
__device__            float g_invdeg[I_NN];
__device__            int   g_cnt[NTOT];      // INVARIANT: zero at kernel_launch entry
__device__            int   g_off[NTOT];
__device__            int   g_cur[NTOT];
__device__            int   g_srcA[ETOT];
__device__ __align__(16) float g_G[RR][DT * DT];
__device__ __align__(16) float g_z[RR][BB * DT];

// ---------------- launch 1: init (copies/coeffs) + histogram -------------
__global__ void k_init_hist(const float* __restrict__ ue, const float* __restrict__ ie,
                            const int* __restrict__ ubd, const int* __restrict__ igd,
                            const float* __restrict__ mgnn,
                            const int* __restrict__ rel_r, const int* __restrict__ tr_c,
                            const int* __restrict__ ig_r) {
    int t = blockIdx.x * blockDim.x + threadIdx.x;
    if (t < ETOT) {
        int d;
        if (t < EB2)       d = DBU + rel_r[t];
        else if (t < EB3)  d = DB2 + tr_c[t - EB2];
        else if (t < EB4)  d = DB3 + ig_r[t - EB3];
        else               d = DB4 + ig_r[E_II + (t - EB4)];
        atomicAdd(&g_cnt[d], 1);
    }
    if (t < U_NN) {
        float m0 = mgnn[0], m1 = mgnn[1];
        float mx = fmaxf(m0, m1);
        float e0 = expf(m0 - mx), e1 = expf(m1 - mx);
        float inv = 1.0f / (e0 + e1);
        float w0 = e0 * inv, w1 = e1 * inv;
        float d0 = (float)ubd[t * 2 + 0], d1 = (float)ubd[t * 2 + 1];
        float itot = 1.0f / (d0 * w0 + d1 * w1 + EPSV);
        g_cuser[t * 2 + 0] = d0 * w0 * itot / (d0 + EPSV);
        g_cuser[t * 2 + 1] = d1 * w1 * itot / (d1 + EPSV);
    }
    if (t < I_NN) {
        g_invig[0][t] = 1.0f / ((float)igd[0 * I_NN + t] + EPSV);
        g_invig[1][t] = 1.0f / ((float)igd[1 * I_NN + t] + EPSV);
    }
    int nU = U_NN * DD;
    if (t < nU) {
        int u = t >> 6, c = t & 63;
        g_Uf[u * DT + c] = ue[t];
    } else if (t < nU + I_NN * DD) {
        int j = t - nU;
        int i = j >> 6, c = j & 63;
        float v = ie[j];
        g_If[i * DT + c] = v;
        g_Sf[0][i * DT + c] = v;
        g_Sf[1][i * DT + c] = v;
    }
}

// ---------------- launch 2: scan (offsets + cursors + invdeg) -------------
__global__ void k_scan() {
    __shared__ int sh[1024];
    const int DBv[4] = {DBU, DB2, DB3, DB4};
    const int DSv[4] = {U_NN, I_NN, I_NN, I_NN};
    int gsel = blockIdx.x;
    int base = DBv[gsel], size = DSv[gsel];
    int t = threadIdx.x;
    int chunk = (size + 1023) >> 10;
    int lo = t * chunk;
    int hi = lo + chunk; if (hi > size) hi = size;
    if (lo > size) lo = size;
    int s = 0;
    for (int i = lo; i < hi; i++) s += g_cnt[base + i];
    sh[t] = s;
    __syncthreads();
    for (int off = 1; off < 1024; off <<= 1) {
        int v = (t >= off) ? sh[t - off] : 0;
        __syncthreads();
        sh[t] += v;
        __syncthreads();
    }
    int run = (t > 0) ? sh[t - 1] : 0;
    for (int i = lo; i < hi; i++) {
        g_off[base + i] = run;
        g_cur[base + i] = run;
        run += g_cnt[base + i];
    }
    if (gsel == 1) {
        for (int i = lo; i < hi; i++)
            g_invdeg[i] = 1.0f / ((float)g_cnt[DB2 + i] + EPSV);
    }
}

// ---------------- launch 3: place ----------------
__global__ void k_place_all(const int* __restrict__ rel_r, const int* __restrict__ rel_c,
                            const int* __restrict__ tr_r, const int* __restrict__ tr_c,
                            const int* __restrict__ ig_r, const int* __restrict__ ig_c) {
    int e = blockIdx.x * blockDim.x + threadIdx.x;
    if (e >= ETOT) return;
    int d, src, ebase;
    if (e < EB2) {
        d = DBU + rel_r[e];
        src = rel_c[e] + ((e >= E_UI) ? RBIT : 0);
        ebase = EBU;
    } else if (e < EB3) {
        int j = e - EB2; d = DB2 + tr_c[j]; src = tr_r[j]; ebase = EB2;
    } else if (e < EB4) {
        int j = e - EB3; d = DB3 + ig_r[j]; src = ig_c[j]; ebase = EB3;
    } else {
        int j = e - EB4; d = DB4 + ig_r[E_II + j]; src = ig_c[E_II + j]; ebase = EB4;
    }
    int p = atomicAdd(&g_cur[d], 1);
    g_srcA[ebase + p] = src;
}

// ---------------- gather: lane owns 2 columns, broadcast idx loads --------
// fb = feature base + colOff + 2*lane ; returns this lane's float2 partial sum.
template <bool WEIGHTED>
__device__ __forceinline__ float2 gather_f2(const int* __restrict__ lst, int deg,
                                            const float* __restrict__ fb,
                                            float c0, float c1) {
    float ax0 = 0.f, ay0 = 0.f, ax1 = 0.f, ay1 = 0.f;
    float ax2 = 0.f, ay2 = 0.f, ax3 = 0.f, ay3 = 0.f;
    int j = 0;
    for (; j + 8 <= deg; j += 8) {
        int p0 = __ldg(lst + j + 0), p1 = __ldg(lst + j + 1);
        int p2 = __ldg(lst + j + 2), p3 = __ldg(lst + j + 3);
        int p4 = __ldg(lst + j + 4), p5 = __ldg(lst + j + 5);
        int p6 = __ldg(lst + j + 6), p7 = __ldg(lst + j + 7);
        float w0 = 1.f, w1 = 1.f, w2 = 1.f, w3 = 1.f;
        float w4 = 1.f, w5 = 1.f, w6 = 1.f, w7 = 1.f;
        if (WEIGHTED) {
            w0 = (p0 & RBIT) ? c1 : c0; p0 &= 0xFFFF;
            w1 = (p1 & RBIT) ? c1 : c0; p1 &= 0xFFFF;
            w2 = (p2 & RBIT) ? c1 : c0; p2 &= 0xFFFF;
            w3 = (p3 & RBIT) ? c1 : c0; p3 &= 0xFFFF;
            w4 = (p4 & RBIT) ? c1 : c0; p4 &= 0xFFFF;
            w5 = (p5 & RBIT) ? c1 : c0; p5 &= 0xFFFF;
            w6 = (p6 & RBIT) ? c1 : c0; p6 &= 0xFFFF;
            w7 = (p7 & RBIT) ? c1 : c0; p7 &= 0xFFFF;
        }
        float2 v0 = *reinterpret_cast<const float2*>(fb + (long)p0 * DT);
        float2 v1 = *reinterpret_cast<const float2*>(fb + (long)p1 * DT);
        float2 v2 = *reinterpret_cast<const float2*>(fb + (long)p2 * DT);
        float2 v3 = *reinterpret_cast<const float2*>(fb + (long)p3 * DT);
        float2 v4 = *reinterpret_cast<const float2*>(fb + (long)p4 * DT);
        float2 v5 = *reinterpret_cast<const float2*>(fb + (long)p5 * DT);
        float2 v6 = *reinterpret_cast<const float2*>(fb + (long)p6 * DT);
        float2 v7 = *reinterpret_cast<const float2*>(fb + (long)p7 * DT);
        ax0 += w0 * v0.x; ay0 += w0 * v0.y;
        ax1 += w1 * v1.x; ay1 += w1 * v1.y;
        ax2 += w2 * v2.x; ay2 += w2 * v2.y;
        ax3 += w3 * v3.x; ay3 += w3 * v3.y;
        ax0 += w4 * v4.x; ay0 += w4 * v4.y;
        ax1 += w5 * v5.x; ay1 += w5 * v5.y;
        ax2 += w6 * v6.x; ay2 += w6 * v6.y;
        ax3 += w7 * v7.x; ay3 += w7 * v7.y;
    }
    for (; j < deg; j++) {
        int p = __ldg(lst + j);
        float w = 1.f;
        if (WEIGHTED) { w = (p & RBIT) ? c1 : c0; p &= 0xFFFF; }
        float2 v = *reinterpret_cast<const float2*>(fb + (long)p * DT);
        ax0 += w * v.x; ay0 += w * v.y;
    }
    return make_float2(ax0 + ax1 + ax2 + ax3, ay0 + ay1 + ay2 + ay3);
}

// ---------------- launch 4/6: fused gather (warp per destination) ---------
__global__ void __launch_bounds__(256, 6) k_gather_all(int colOff) {
    int w = (blockIdx.x * blockDim.x + threadIdx.x) >> 5;
    if (w >= U_NN + 3 * I_NN) return;
    int lane = threadIdx.x & 31;
    int c2 = lane * 2;
    float2 r;
    float* dst;
    int row;
    if (w < U_NN) {
        int u = w;
        float c0 = g_cuser[u * 2 + 0], c1 = g_cuser[u * 2 + 1];
        r = gather_f2<true>(g_srcA + g_off[DBU + u], g_cnt[DBU + u],
                            g_If + colOff + c2, c0, c1);
        dst = g_Uagg; row = u;
    } else {
        int v = w - U_NN;
        int gsel = v / I_NN;
        int i = v - gsel * I_NN;
        float2 a; float c;
        if (gsel == 0) {
            a = gather_f2<false>(g_srcA + EB2 + g_off[DB2 + i], g_cnt[DB2 + i],
                                 g_Uf + colOff + c2, 0.f, 0.f);
            c = g_invdeg[i]; dst = g_Iagg;
        } else if (gsel == 1) {
            a = gather_f2<false>(g_srcA + EB3 + g_off[DB3 + i], g_cnt[DB3 + i],
                                 g_If + colOff + c2, 0.f, 0.f);
            c = g_invig[0][i]; dst = g_IGagg[0];
        } else {
            a = gather_f2<false>(g_srcA + EB4 + g_off[DB4 + i], g_cnt[DB4 + i],
                                 g_If + colOff + c2, 0.f, 0.f);
            c = g_invig[1][i]; dst = g_IGagg[1];
        }
        r = make_float2(a.x * c, a.y * c);
        row = i;
    }
    *reinterpret_cast<float2*>(&dst[(long)row * DD + c2]) = r;
}

// ---------------- launch 5/7: fused dense projections ----------------
__global__ void k_gemm_all(const float* __restrict__ W_ui_l,
                           const float* __restrict__ W_ii0_l,
                           const float* __restrict__ W_ii1_l, int colOut) {
    __shared__ __align__(16) float Ws[64 * 64];
    __shared__ __align__(16) float As[64 * 68];
    int sel = blockIdx.y;
    const float* src; float* dst; const float* W; int N;
    if (sel == 0)      { src = g_Uagg;     dst = g_Uf;    W = W_ui_l;  N = U_NN; }
    else if (sel == 1) { src = g_Iagg;     dst = g_If;    W = W_ui_l;  N = I_NN; }
    else if (sel == 2) { src = g_IGagg[0]; dst = g_Sf[0]; W = W_ii0_l; N = I_NN; }
    else               { src = g_IGagg[1]; dst = g_Sf[1]; W = W_ii1_l; N = I_NN; }
    int row0 = blockIdx.x * 64;
    if (row0 >= N) return;
    int tid = threadIdx.x;

    for (int i = tid; i < 4096; i += 256) Ws[i] = W[i];
    for (int i = tid; i < 4096; i += 256) {
        int rr = i >> 6, k = i & 63;
        float v = (row0 + rr < N) ? src[(long)(row0 + rr) * DD + k] : 0.f;
        As[k * 68 + rr] = v;
    }
    __syncthreads();

    int cg = tid & 15, rg = tid >> 4;
    float acc[4][4];
#pragma unroll
    for (int i = 0; i < 4; i++)
#pragma unroll
        for (int j = 0; j < 4; j++) acc[i][j] = 0.f;

#pragma unroll 8
    for (int k = 0; k < 64; k++) {
        float4 a4 = *reinterpret_cast<const float4*>(&As[k * 68 + rg * 4]);
        float4 w4 = *reinterpret_cast<const float4*>(&Ws[k * 64 + cg * 4]);
        float a[4] = {a4.x, a4.y, a4.z, a4.w};
        float w[4] = {w4.x, w4.y, w4.z, w4.w};
#pragma unroll
        for (int i = 0; i < 4; i++)
#pragma unroll
            for (int j = 0; j < 4; j++) acc[i][j] += a[i] * w[j];
    }
#pragma unroll
    for (int i = 0; i < 4; i++) {
        int row = row0 + rg * 4 + i;
        if (row < N) {
            float4 o = make_float4(acc[i][0], acc[i][1], acc[i][2], acc[i][3]);
            *reinterpret_cast<float4*>(&dst[(long)row * DT + colOut + cg * 4]) = o;
        }
    }
}

// ---------------- scoring ----------------
__global__ void k_G(const float* __restrict__ bW, float* out, int lossIdx) {
    __shared__ float Asm[32 * 192];
    __shared__ float Bsm[32 * 192];
    if (blockIdx.x == 0 && blockIdx.y == 0 && blockIdx.z == 0 && threadIdx.x == 0)
        out[lossIdx] = 0.f;
    int r = blockIdx.z;
    const float* W = bW + (long)r * DT * DT;
    int i0 = blockIdx.x * 32, j0 = blockIdx.y * 32;
    for (int t = threadIdx.x; t < 32 * 192; t += 256) {
        Asm[t] = W[(long)(i0 + t / 192) * DT + (t % 192)];
        Bsm[t] = W[(long)(j0 + t / 192) * DT + (t % 192)];
    }
    __syncthreads();
    int tj = threadIdx.x & 15, ti = threadIdx.x >> 4;
    float acc[2][2] = {{0.f, 0.f}, {0.f, 0.f}};
    for (int k = 0; k < 192; k++) {
        float a0 = Asm[(ti * 2 + 0) * 192 + k];
        float a1 = Asm[(ti * 2 + 1) * 192 + k];
        float b0 = Bsm[(tj * 2 + 0) * 192 + k];
        float b1 = Bsm[(tj * 2 + 1) * 192 + k];
        acc[0][0] += a0 * b0; acc[0][1] += a0 * b1;
        acc[1][0] += a1 * b0; acc[1][1] += a1 * b1;
    }
#pragma unroll
    for (int i = 0; i < 2; i++)
#pragma unroll
        for (int j = 0; j < 2; j++)
            g_G[r][(long)(i0 + ti * 2 + i) * DT + (j0 + tj * 2 + j)] = acc[i][j];
}

// block per (b,r): aggregate batched user's rel-r subset of merged list, then z = agg @ G
__global__ void k_aggsel_z(const int* __restrict__ users, const int* __restrict__ ubd) {
    __shared__ float as[DT];
    int b = blockIdx.x, r = blockIdx.y, c = threadIdx.x;
    int u = users[b];
    const int* lst = g_srcA + g_off[DBU + u];
    int deg = g_cnt[DBU + u];
    int want = r ? RBIT : 0;
    const float* S = g_Sf[r];
    float a0 = 0.f;
    for (int j = 0; j < deg; j++) {
        int p = __ldg(&lst[j]);
        if ((p & RBIT) == want)
            a0 += S[(long)(p & 0xFFFF) * DT + c];
    }
    float coeff = 1.0f / ((float)ubd[u * 2 + r] + EPSV);
    as[c] = a0 * coeff;
    __syncthreads();
    float acc = 0.f;
    const float* G = g_G[r];
#pragma unroll 4
    for (int k = 0; k < DT; k++) acc += as[k] * G[(long)k * DT + c];
    g_z[r][(long)b * DT + c] = acc;
}

// warp per (b,k); also restores the g_cnt==0 invariant for the next call
__global__ void k_score(const int* __restrict__ users, const int* __restrict__ items,
                        float* out, int lossIdx) {
    __shared__ float l2blk;
    int tg = blockIdx.x * blockDim.x + threadIdx.x;
    if (tg < NTOT) g_cnt[tg] = 0;
    if (threadIdx.x == 0) l2blk = 0.f;
    __syncthreads();
    int w = tg >> 5;
    int lane = threadIdx.x & 31;
    if (w < BB * KK) {
        int b = w / KK;
        int kk = w - b * KK;
        int u = users[b];
        int it = items[w];
        float s1 = 0.f, s2a = 0.f, s2b = 0.f, l2i = 0.f, l2u = 0.f;
        for (int c = lane; c < DT; c += 32) {
            float bu = g_Uf[(long)u * DT + c];
            float bi = g_If[(long)it * DT + c];
            s1 += bu * bi;
            l2i += bi * bi;
            if (kk == 0) l2u += bu * bu;
            s2a += g_z[0][(long)b * DT + c] * g_Sf[0][(long)it * DT + c];
            s2b += g_z[1][(long)b * DT + c] * g_Sf[1][(long)it * DT + c];
        }
#pragma unroll
        for (int off = 16; off; off >>= 1) {
            s1  += __shfl_down_sync(0xffffffffu, s1, off);
            s2a += __shfl_down_sync(0xffffffffu, s2a, off);
            s2b += __shfl_down_sync(0xffffffffu, s2b, off);
            l2i += __shfl_down_sync(0xffffffffu, l2i, off);
            if (kk == 0) l2u += __shfl_down_sync(0xffffffffu, l2u, off);
        }
        if (lane == 0) {
            out[w] = 0.5f * s1 + 0.25f * (s2a + s2b);
            atomicAdd(&l2blk, l2i + (kk == 0 ? (float)KK * l2u : 0.f));
        }
    }
    __syncthreads();
    if (threadIdx.x == 0) atomicAdd(out + lossIdx, 1e-4f * l2blk);
}

// ---------------- launch ----------------
extern "C" void kernel_launch(void* const* d_in, const int* in_sizes, int n_in,
                              void* d_out, int out_size) {
    const float* ue    = (const float*)d_in[0];
    const float* ie    = (const float*)d_in[1];
    const float* W_ui  = (const float*)d_in[2];
    const float* W_ii  = (const float*)d_in[3];
    const float* bW    = (const float*)d_in[4];
    const float* mgnn  = (const float*)d_in[5];
    const int* rel_r   = (const int*)d_in[6];
    const int* rel_c   = (const int*)d_in[7];
    const int* tr_r    = (const int*)d_in[8];
    const int* tr_c    = (const int*)d_in[9];
    const int* ig_r    = (const int*)d_in[10];
    const int* ig_c    = (const int*)d_in[11];
    const int* ubd     = (const int*)d_in[12];
    const int* igd     = (const int*)d_in[13];
    const int* users   = (const int*)d_in[14];
    const int* items   = (const int*)d_in[15];
    float* out = (float*)d_out;
    int lossIdx = out_size - 1;

    const int T = 256;
    auto g = [](long n, int t) { return (int)((n + t - 1) / t); };

    // 1-3: init + CSR build (g_cnt zero-at-entry invariant; k_score restores it)
    k_init_hist<<<g((long)(U_NN + I_NN) * DD, T), T>>>(ue, ie, ubd, igd, mgnn,
                                                       rel_r, tr_c, ig_r);
    k_scan<<<4, 1024>>>();
    k_place_all<<<g(ETOT, T), T>>>(rel_r, rel_c, tr_r, tr_c, ig_r, ig_c);

    // 4-7: two propagation layers
    for (int l = 0; l < LL; l++) {
        k_gather_all<<<g((long)(U_NN + 3 * I_NN) * 32, T), T>>>(l * DD);
        dim3 gg(g(U_NN, 64), 4);
        k_gemm_all<<<gg, 256>>>(W_ui + (long)l * DD * DD,
                                W_ii + (long)(0 * LL + l) * DD * DD,
                                W_ii + (long)(1 * LL + l) * DD * DD,
                                (l + 1) * DD);
    }

    // 8-10: scoring
    {
        dim3 ggG(6, 6, 2);
        k_G<<<ggG, 256>>>(bW, out, lossIdx);
    }
    {
        dim3 gz(BB, RR);
        k_aggsel_z<<<gz, DT>>>(users, ubd);
    }
    k_score<<<g((long)BB * KK * 32, T), T>>>(users, items, out, lossIdx);
}